// round 14
// baseline (speedup 1.0000x reference)
#include <cuda_runtime.h>
#include <cuda_bf16.h>
#include <cstdint>

#define CC 19
#define NP 361
#define DD 256
#define BB 32
#define HH 8
#define HDIM 32
#define MX (BB*NP)   // 11552
#define MQ (BB*CC)   // 608
#define NKV 512
#define NTOT (CC*NKV) // 9728

// ---------------- scratch (device globals: no allocations allowed) ----------
__device__ float g_KT[(size_t)CC*BB*DD*NP];  // K transposed: [c][b][e][pos]
__device__ float g_V [(size_t)CC*BB*NP*DD];  // [c][b][pos][e]
__device__ float g_Q [(size_t)CC*BB*CC*DD];  // [c][b][j][e]
__device__ float g_AO[(size_t)CC*BB*CC*DD];
__device__ float g_Mc[(size_t)CC*DD*DD];
__device__ float g_bc[(size_t)CC*DD];

// bf16 split operands for tensor-core GEMMs
__device__ __nv_bfloat16 g_xh[(size_t)MX*DD];
__device__ __nv_bfloat16 g_xl[(size_t)MX*DD];
__device__ __nv_bfloat16 g_wh[(size_t)CC*768*DD];
__device__ __nv_bfloat16 g_wl[(size_t)CC*768*DD];

// ---------------- fused fp32 -> bf16 hi/lo split (x and w_in in one launch) ----
#define N4X ((MX*DD)/4)
#define N4W ((CC*768*DD)/4)
__global__ void split_all(const float* __restrict__ x, const float* __restrict__ w) {
    int i = blockIdx.x * 256 + threadIdx.x;
    const float* src;
    __nv_bfloat16 *h, *l;
    int idx;
    if (i < N4X) { src = x; h = g_xh; l = g_xl; idx = i; }
    else if (i < N4X + N4W) { src = w; h = g_wh; l = g_wl; idx = i - N4X; }
    else return;
    float4 v = ((const float4*)src)[idx];
    __nv_bfloat16 h0 = __float2bfloat16(v.x);
    __nv_bfloat16 h1 = __float2bfloat16(v.y);
    __nv_bfloat16 h2 = __float2bfloat16(v.z);
    __nv_bfloat16 h3 = __float2bfloat16(v.w);
    __nv_bfloat162 hh0 = {h0, h1}, hh1 = {h2, h3};
    __nv_bfloat162 ll0 = {__float2bfloat16(v.x - __bfloat162float(h0)),
                          __float2bfloat16(v.y - __bfloat162float(h1))};
    __nv_bfloat162 ll1 = {__float2bfloat16(v.z - __bfloat162float(h2)),
                          __float2bfloat16(v.w - __bfloat162float(h3))};
    ((__nv_bfloat162*)h)[idx*2+0] = hh0;
    ((__nv_bfloat162*)h)[idx*2+1] = hh1;
    ((__nv_bfloat162*)l)[idx*2+0] = ll0;
    ((__nv_bfloat162*)l)[idx*2+1] = ll1;
}

// ---------------- HMMA helpers -------------------------------------------------
__device__ __forceinline__ void mma16816(float* d, const uint32_t* a, const uint32_t* b) {
    asm volatile(
        "mma.sync.aligned.m16n8k16.row.col.f32.bf16.bf16.f32 "
        "{%0,%1,%2,%3}, {%4,%5,%6,%7}, {%8,%9}, {%0,%1,%2,%3};"
        : "+f"(d[0]), "+f"(d[1]), "+f"(d[2]), "+f"(d[3])
        : "r"(a[0]), "r"(a[1]), "r"(a[2]), "r"(a[3]), "r"(b[0]), "r"(b[1]));
}
__device__ __forceinline__ void ldsm4(uint32_t* r, uint32_t addr) {
    asm volatile("ldmatrix.sync.aligned.m8n8.x4.shared.b16 {%0,%1,%2,%3}, [%4];"
                 : "=r"(r[0]), "=r"(r[1]), "=r"(r[2]), "=r"(r[3]) : "r"(addr));
}
__device__ __forceinline__ void cp16(uint32_t saddr, const void* g) {
    asm volatile("cp.async.cg.shared.global [%0], [%1], 16;\n" :: "r"(saddr), "l"(g));
}
__device__ __forceinline__ uint32_t smem_u32(const void* p) {
    uint32_t a;
    asm("{ .reg .u64 t; cvta.to.shared.u64 t, %1; cvt.u32.u64 %0, t; }" : "=r"(a) : "l"(p));
    return a;
}

// ---------------- bf16x3 tensor-core KV GEMM (4-stage, 2 CTAs/SM) --------------
#define ROWB 48
#define ARRB (128*ROWB)
#define STGB (4*ARRB)
#define KV_SMEM (4*STGB)              // 98304 B

__global__ __launch_bounds__(256, 2)
void gemm_kv_mma(const float* __restrict__ b_in) {
    extern __shared__ char smraw[];
    const uint32_t sbase = smem_u32(smraw);

    const int tid  = threadIdx.x;
    const int warp = tid >> 5, lane = tid & 31;
    const int m0   = blockIdx.x * 128;
    const int n0g  = blockIdx.y * 128;
    const int c    = n0g / NKV;
    const int e0   = n0g % NKV;

    const int wm = (warp >> 2) * 64;
    const int wn = (warp & 3) * 32;

    uint32_t aoff[4], boff[2];
    {
        int mr = (lane & 7) + ((lane >> 3) & 1) * 8;
        int kb = (lane >> 4) * 16;
        #pragma unroll
        for (int ms = 0; ms < 4; ms++) aoff[ms] = (uint32_t)((wm + ms*16 + mr) * ROWB + kb);
        int nr  = (lane & 7) + ((lane >> 4) & 1) * 8;
        int kbb = ((lane >> 3) & 1) * 16;
        #pragma unroll
        for (int n2 = 0; n2 < 2; n2++) boff[n2] = (uint32_t)((wn + n2*16 + nr) * ROWB + kbb);
    }

    const int lrow = tid >> 1;
    const int lchk = tid & 1;
    int am = m0 + lrow; if (am > MX-1) am = MX-1;
    const __nv_bfloat16* pxh = g_xh + (size_t)am * DD + lchk*8;
    const __nv_bfloat16* pxl = g_xl + (size_t)am * DD + lchk*8;
    const size_t wrow = ((size_t)c * 768 + 256 + e0 + lrow) * DD + lchk*8;
    const __nv_bfloat16* pwh = g_wh + wrow;
    const __nv_bfloat16* pwl = g_wl + wrow;
    const uint32_t so = (uint32_t)(lrow*ROWB + lchk*16);

    auto issue = [&](int kt) {
        uint32_t s0 = sbase + (uint32_t)(kt & 3) * STGB + so;
        int k0 = kt * 16;
        cp16(s0 + 0*ARRB, pxh + k0);
        cp16(s0 + 1*ARRB, pxl + k0);
        cp16(s0 + 2*ARRB, pwh + k0);
        cp16(s0 + 3*ARRB, pwl + k0);
        asm volatile("cp.async.commit_group;");
    };

    uint32_t ah[2][4][4], al[2][4][4], bh[2][4][2], bl[2][4][2];
    auto ldfrags = [&](int buf, uint32_t base) {
        #pragma unroll
        for (int ms = 0; ms < 4; ms++) {
            ldsm4(ah[buf][ms], base + 0*ARRB + aoff[ms]);
            ldsm4(al[buf][ms], base + 1*ARRB + aoff[ms]);
        }
        #pragma unroll
        for (int n2 = 0; n2 < 2; n2++) {
            ldsm4(&bh[buf][n2*2][0], base + 2*ARRB + boff[n2]);
            ldsm4(&bl[buf][n2*2][0], base + 3*ARRB + boff[n2]);
        }
    };

    float acc[4][4][4];
    #pragma unroll
    for (int i = 0; i < 4; i++)
        #pragma unroll
        for (int j = 0; j < 4; j++)
            #pragma unroll
            for (int k = 0; k < 4; k++) acc[i][j][k] = 0.f;

    issue(0); issue(1); issue(2); issue(3);
    asm volatile("cp.async.wait_group 3;");
    __syncthreads();
    ldfrags(0, sbase + 0*STGB);

    #pragma unroll
    for (int kt = 0; kt < 16; kt++) {
        const int cur = kt & 1, nxt = cur ^ 1;
        // ensure stage kt+1 landed (pending groups after wait: 2 while still issuing)
        if (kt < 13)       asm volatile("cp.async.wait_group 2;");
        else if (kt == 13) asm volatile("cp.async.wait_group 1;");
        else if (kt == 14) asm volatile("cp.async.wait_group 0;");
        __syncthreads();
        if (kt + 4 < 16) issue(kt + 4);                 // refill stage kt&3
        if (kt + 1 < 16) ldfrags(nxt, sbase + (uint32_t)((kt+1) & 3)*STGB);

        #pragma unroll
        for (int ms = 0; ms < 4; ms++)
            #pragma unroll
            for (int ns = 0; ns < 4; ns++) {
                mma16816(acc[ms][ns], ah[cur][ms], bh[cur][ns]);
                mma16816(acc[ms][ns], ah[cur][ms], bl[cur][ns]);
                mma16816(acc[ms][ns], al[cur][ms], bh[cur][ns]);
            }
    }

    // epilogue: +bias; K goes out transposed ([e][pos]), V normal ([pos][e])
    const int qr = lane >> 2, qc = lane & 3;
    #pragma unroll
    for (int ns = 0; ns < 4; ns++) {
        int e = e0 + wn + ns*8 + qc*2;
        float b0 = b_in[c*768 + 256 + e];
        float b1 = b_in[c*768 + 256 + e + 1];
        bool isK = (e < 256);
        int col = isK ? e : e - 256;
        #pragma unroll
        for (int ms = 0; ms < 4; ms++) {
            int gm0 = m0 + wm + ms*16 + qr;
            #pragma unroll
            for (int half = 0; half < 2; half++) {
                int gm = gm0 + half*8;
                if (gm >= MX) continue;
                int bb = gm / NP, pos = gm % NP;
                float vx = acc[ms][ns][half*2+0] + b0;
                float vy = acc[ms][ns][half*2+1] + b1;
                size_t cb = (size_t)c*BB + bb;
                if (isK) {
                    g_KT[(cb*DD + col    )*NP + pos] = vx;
                    g_KT[(cb*DD + col + 1)*NP + pos] = vy;
                } else {
                    float2 v; v.x = vx; v.y = vy;
                    *(float2*)(g_V + (cb*NP + pos)*DD + col) = v;
                }
            }
        }
    }
}

// ---------------- Q projection GEMM (bf16x3 HMMA, gathered A rows, 3-stage) -----
#define Q_SMEM (3*STGB)               // 73728 B
__global__ __launch_bounds__(256, 2)
void gemm_q_mma(const float* __restrict__ b_in) {
    extern __shared__ char smraw[];
    const uint32_t sbase = smem_u32(smraw);

    const int tid  = threadIdx.x;
    const int warp = tid >> 5, lane = tid & 31;
    const int m0   = blockIdx.x * 128;
    const int c    = blockIdx.y >> 1;
    const int e0   = (blockIdx.y & 1) * 128;

    const int wm = (warp >> 2) * 64;
    const int wn = (warp & 3) * 32;

    uint32_t aoff[4], boff[2];
    {
        int mr = (lane & 7) + ((lane >> 3) & 1) * 8;
        int kb = (lane >> 4) * 16;
        #pragma unroll
        for (int ms = 0; ms < 4; ms++) aoff[ms] = (uint32_t)((wm + ms*16 + mr) * ROWB + kb);
        int nr  = (lane & 7) + ((lane >> 4) & 1) * 8;
        int kbb = ((lane >> 3) & 1) * 16;
        #pragma unroll
        for (int n2 = 0; n2 < 2; n2++) boff[n2] = (uint32_t)((wn + n2*16 + nr) * ROWB + kbb);
    }

    const int lrow = tid >> 1;
    const int lchk = tid & 1;
    int am = m0 + lrow; if (am > MQ-1) am = MQ-1;
    int xrow = (am / CC) * NP + c * CC + (am % CC);
    const __nv_bfloat16* pxh = g_xh + (size_t)xrow * DD + lchk*8;
    const __nv_bfloat16* pxl = g_xl + (size_t)xrow * DD + lchk*8;
    const size_t wrow = ((size_t)c * 768 + e0 + lrow) * DD + lchk*8;
    const __nv_bfloat16* pwh = g_wh + wrow;
    const __nv_bfloat16* pwl = g_wl + wrow;
    const uint32_t so = (uint32_t)(lrow*ROWB + lchk*16);

    auto issue = [&](int kt) {
        uint32_t s0 = sbase + (uint32_t)(kt % 3) * STGB + so;
        int k0 = kt * 16;
        cp16(s0 + 0*ARRB, pxh + k0);
        cp16(s0 + 1*ARRB, pxl + k0);
        cp16(s0 + 2*ARRB, pwh + k0);
        cp16(s0 + 3*ARRB, pwl + k0);
        asm volatile("cp.async.commit_group;");
    };

    uint32_t ah[2][4][4], al[2][4][4], bh[2][4][2], bl[2][4][2];
    auto ldfrags = [&](int buf, uint32_t base) {
        #pragma unroll
        for (int ms = 0; ms < 4; ms++) {
            ldsm4(ah[buf][ms], base + 0*ARRB + aoff[ms]);
            ldsm4(al[buf][ms], base + 1*ARRB + aoff[ms]);
        }
        #pragma unroll
        for (int n2 = 0; n2 < 2; n2++) {
            ldsm4(&bh[buf][n2*2][0], base + 2*ARRB + boff[n2]);
            ldsm4(&bl[buf][n2*2][0], base + 3*ARRB + boff[n2]);
        }
    };

    float acc[4][4][4];
    #pragma unroll
    for (int i = 0; i < 4; i++)
        #pragma unroll
        for (int j = 0; j < 4; j++)
            #pragma unroll
            for (int k = 0; k < 4; k++) acc[i][j][k] = 0.f;

    issue(0); issue(1); issue(2);
    asm volatile("cp.async.wait_group 2;");
    __syncthreads();
    ldfrags(0, sbase + 0*STGB);

    #pragma unroll
    for (int kt = 0; kt < 16; kt++) {
        const int cur = kt & 1, nxt = cur ^ 1;
        if (kt < 14)       asm volatile("cp.async.wait_group 1;");
        else if (kt == 14) asm volatile("cp.async.wait_group 0;");
        __syncthreads();
        if (kt + 3 < 16) issue(kt + 3);
        if (kt + 1 < 16) ldfrags(nxt, sbase + (uint32_t)((kt+1)%3)*STGB);

        #pragma unroll
        for (int ms = 0; ms < 4; ms++)
            #pragma unroll
            for (int ns = 0; ns < 4; ns++) {
                mma16816(acc[ms][ns], ah[cur][ms], bh[cur][ns]);
                mma16816(acc[ms][ns], ah[cur][ms], bl[cur][ns]);
                mma16816(acc[ms][ns], al[cur][ms], bh[cur][ns]);
            }
    }

    const int qr = lane >> 2, qc = lane & 3;
    #pragma unroll
    for (int ns = 0; ns < 4; ns++) {
        int e = e0 + wn + ns*8 + qc*2;
        float b0 = b_in[c*768 + e];
        float b1 = b_in[c*768 + e + 1];
        #pragma unroll
        for (int ms = 0; ms < 4; ms++) {
            int gm0 = m0 + wm + ms*16 + qr;
            #pragma unroll
            for (int half = 0; half < 2; half++) {
                int gm = gm0 + half*8;
                if (gm >= MQ) continue;
                float2 v;
                v.x = acc[ms][ns][half*2+0] + b0;
                v.y = acc[ms][ns][half*2+1] + b1;
                *(float2*)(g_Q + ((size_t)c*MQ + gm)*DD + e) = v;
            }
        }
    }
}

// ---------------- combined weight: Mc[c] = w_fuse @ w_out[c] -----------------
__global__ __launch_bounds__(256, 2)
void gemm_comb(const float* __restrict__ w_fuse, const float* __restrict__ w_out) {
    const int c  = blockIdx.z;
    const int m0 = blockIdx.x * 128;
    const int n0 = blockIdx.y * 128;
    __shared__ float As[8][128];
    __shared__ float Bs[8][128];
    const int tid  = threadIdx.x;
    const int aRow = tid >> 1, aCol = (tid & 1) << 2;
    const int bK   = tid >> 5, bN = (tid & 31) << 2;

    const float* Ap = w_fuse + (size_t)(m0 + aRow) * DD + aCol;
    const float* Bbase = w_out + (size_t)c * DD * DD;

    const int ty = tid >> 4, tx = tid & 15;
    float acc[8][8];
    #pragma unroll
    for (int i = 0; i < 8; i++)
        #pragma unroll
        for (int j = 0; j < 8; j++) acc[i][j] = 0.f;

    for (int kt = 0; kt < DD; kt += 8) {
        float4 a = *(const float4*)(Ap + kt);
        float4 b = *(const float4*)(Bbase + (size_t)(kt + bK) * DD + n0 + bN);
        As[aCol+0][aRow]=a.x; As[aCol+1][aRow]=a.y;
        As[aCol+2][aRow]=a.z; As[aCol+3][aRow]=a.w;
        *(float4*)&Bs[bK][bN] = b;
        __syncthreads();
        #pragma unroll
        for (int k = 0; k < 8; k++) {
            float ra[8], rb[8];
            *(float4*)&ra[0] = *(const float4*)&As[k][ty*8];
            *(float4*)&ra[4] = *(const float4*)&As[k][ty*8+4];
            *(float4*)&rb[0] = *(const float4*)&Bs[k][tx*8];
            *(float4*)&rb[4] = *(const float4*)&Bs[k][tx*8+4];
            #pragma unroll
            for (int i = 0; i < 8; i++)
                #pragma unroll
                for (int j = 0; j < 8; j++)
                    acc[i][j] = fmaf(ra[i], rb[j], acc[i][j]);
        }
        __syncthreads();
    }

    #pragma unroll
    for (int i = 0; i < 8; i++) {
        int m = m0 + ty*8 + i;
        float* op = g_Mc + ((size_t)c*DD + m)*DD + n0 + tx*8;
        #pragma unroll
        for (int j = 0; j < 8; j += 4) {
            float4 v; v.x=acc[i][j]; v.y=acc[i][j+1]; v.z=acc[i][j+2]; v.w=acc[i][j+3];
            *(float4*)(op + j) = v;
        }
    }
}

// ---------------- combined bias (warp per output) ------------------------------
__global__ void bias_comb(const float* __restrict__ w_fuse,
                          const float* __restrict__ b_out,
                          const float* __restrict__ b_fuse) {
    int c = blockIdx.x;
    int e = blockIdx.y * 8 + (threadIdx.x >> 5);
    int lane = threadIdx.x & 31;
    const float* wf = w_fuse + (size_t)e * DD;
    const float* bo = b_out + c * DD;
    float s = 0.f;
    #pragma unroll
    for (int i = 0; i < 8; i++) s = fmaf(wf[lane + i*32], bo[lane + i*32], s);
    #pragma unroll
    for (int o = 16; o; o >>= 1) s += __shfl_xor_sync(~0u, s, o);
    if (lane == 0) g_bc[c*DD + e] = s + b_fuse[e];
}

// ---------------- attention: one CTA per (h, c, b), coalesced KT reads ---------
__global__ __launch_bounds__(256)
void attn_kernel() {
    __shared__ float S[24][368];     // 35328 B (rows 19..23 = zero pad for PV)
    __shared__ float Qh[CC][36];     // 2736 B
    const int h  = blockIdx.x;
    const int cb = blockIdx.y;       // c*BB + b
    const int c  = cb / BB;
    const int hoff = h * HDIM;
    const int tid  = threadIdx.x;
    const int wid  = tid >> 5, lane = tid & 31;

    const float* KTg = g_KT + ((size_t)cb * DD + hoff) * NP;  // [d][pos]
    const float* Vg  = g_V  + (size_t)cb * NP * DD;
    const float* Qg  = g_Q  + (size_t)cb * CC * DD;
    float*       Og  = g_AO + (size_t)cb * CC * DD;

    // stage Q head-slice (19x32) + zero pad rows of S
    for (int i = tid; i < CC*8; i += 256) {
        int row = i >> 3, q4 = i & 7;
        float4 v = *(const float4*)(Qg + (size_t)row * DD + hoff + q4*4);
        *(float4*)&Qh[row][q4*4] = v;
    }
    for (int i = tid; i < 5*368; i += 256) (&S[19][0])[i] = 0.f;
    __syncthreads();

    const float scale = 0.17677669529663687f;   // 1/sqrt(32)

    // ---- scores + mask (coalesced KT: lane=k, stride-NP per dim) ----
    for (int k = tid; k < NP; k += 256) {
        float kr[HDIM];
        #pragma unroll
        for (int d = 0; d < HDIM; d++) kr[d] = KTg[(size_t)d * NP + k];
        int ki = k / CC, kj = k - ki*CC;
        for (int j = 0; j < CC; j++) {
            const float4* qp = (const float4*)&Qh[j][0];
            float s0 = 0.f, s1 = 0.f, s2 = 0.f, s3 = 0.f;
            #pragma unroll
            for (int q = 0; q < 8; q++) {
                float4 qv = qp[q];
                s0 = fmaf(kr[q*4+0], qv.x, s0);
                s1 = fmaf(kr[q*4+1], qv.y, s1);
                s2 = fmaf(kr[q*4+2], qv.z, s2);
                s3 = fmaf(kr[q*4+3], qv.w, s3);
            }
            float s = (s0 + s1) + (s2 + s3);
            bool ok = (ki == c) | (kj == c) | (ki == j) | (kj == j);
            S[j][k] = ok ? s * scale : -1e30f;
        }
    }
    __syncthreads();

    // ---- softmax, one warp per row ----
    for (int j = wid; j < CC; j += 8) {
        float mx = -1e30f;
        for (int k = lane; k < NP; k += 32) mx = fmaxf(mx, S[j][k]);
        #pragma unroll
        for (int o = 16; o; o >>= 1) mx = fmaxf(mx, __shfl_xor_sync(~0u, mx, o));
        float sum = 0.f;
        for (int k = lane; k < NP; k += 32) {
            float e = __expf(S[j][k] - mx);
            S[j][k] = e; sum += e;
        }
        #pragma unroll
        for (int o = 16; o; o >>= 1) sum += __shfl_xor_sync(~0u, sum, o);
        float inv = 1.f / sum;
        for (int k = lane; k < NP; k += 32) S[j][k] *= inv;
    }
    __syncthreads();

    // ---- P @ V (coalesced global V, x4 unroll, branchless via pad rows) ----
    {
        const int d = lane, jg = wid;
        const float* vp = Vg + hoff + d;
        float o0 = 0.f, o1 = 0.f, o2 = 0.f;
        for (int k = 0; k < 360; k += 4) {
            float v0 = vp[(size_t)(k+0) * DD];
            float v1 = vp[(size_t)(k+1) * DD];
            float v2 = vp[(size_t)(k+2) * DD];
            float v3 = vp[(size_t)(k+3) * DD];
            float4 sA = *(const float4*)&S[jg   ][k];
            float4 sB = *(const float4*)&S[jg+8 ][k];
            float4 sC = *(const float4*)&S[jg+16][k];
            o0 = fmaf(sA.x, v0, o0); o1 = fmaf(sB.x, v0, o1); o2 = fmaf(sC.x, v0, o2);
            o0 = fmaf(sA.y, v1, o0); o1 = fmaf(sB.y, v1, o1); o2 = fmaf(sC.y, v1, o2);
            o0 = fmaf(sA.z, v2, o0); o1 = fmaf(sB.z, v2, o1); o2 = fmaf(sC.z, v2, o2);
            o0 = fmaf(sA.w, v3, o0); o1 = fmaf(sB.w, v3, o1); o2 = fmaf(sC.w, v3, o2);
        }
        {   // tail k = 360
            float v = vp[(size_t)360 * DD];
            o0 = fmaf(S[jg   ][360], v, o0);
            o1 = fmaf(S[jg+8 ][360], v, o1);
            o2 = fmaf(S[jg+16][360], v, o2);
        }
        Og[jg*DD + hoff + d]     = o0;
        Og[(jg+8)*DD + hoff + d] = o1;
        if (jg + 16 < CC) Og[(jg+16)*DD + hoff + d] = o2;
    }
}

// ---------------- out-proj + fuse + residual ----------------------------------
__global__ __launch_bounds__(256, 2)
void out_fuse(const float* __restrict__ x, float* __restrict__ y) {
    const int c  = blockIdx.z;
    const int m0 = blockIdx.x * 128;
    const int n0 = blockIdx.y * 128;
    __shared__ float As[8][128];
    __shared__ float Bs[8][128];
    const int tid   = threadIdx.x;
    const int ldRow = tid >> 1;
    const int ldCol = (tid & 1) << 2;

    int am = m0 + ldRow; if (am > MQ - 1) am = MQ - 1;
    const float* Ap = g_AO + ((size_t)c*MQ + am) * DD + ldCol;
    const float* Bp = g_Mc + ((size_t)c*DD + n0 + ldRow) * DD + ldCol;

    const int ty = tid >> 4, tx = tid & 15;
    float acc[8][8];
    #pragma unroll
    for (int i = 0; i < 8; i++)
        #pragma unroll
        for (int j = 0; j < 8; j++) acc[i][j] = 0.f;

    for (int kt = 0; kt < DD; kt += 8) {
        float4 a = *(const float4*)(Ap + kt);
        float4 b = *(const float4*)(Bp + kt);
        As[ldCol+0][ldRow]=a.x; As[ldCol+1][ldRow]=a.y;
        As[ldCol+2][ldRow]=a.z; As[ldCol+3][ldRow]=a.w;
        Bs[ldCol+0][ldRow]=b.x; Bs[ldCol+1][ldRow]=b.y;
        Bs[ldCol+2][ldRow]=b.z; Bs[ldCol+3][ldRow]=b.w;
        __syncthreads();
        #pragma unroll
        for (int k = 0; k < 8; k++) {
            float ra[8], rb[8];
            *(float4*)&ra[0] = *(const float4*)&As[k][ty*8];
            *(float4*)&ra[4] = *(const float4*)&As[k][ty*8+4];
            *(float4*)&rb[0] = *(const float4*)&Bs[k][tx*8];
            *(float4*)&rb[4] = *(const float4*)&Bs[k][tx*8+4];
            #pragma unroll
            for (int i = 0; i < 8; i++)
                #pragma unroll
                for (int j = 0; j < 8; j++)
                    acc[i][j] = fmaf(ra[i], rb[j], acc[i][j]);
        }
        __syncthreads();
    }

    const float* bcp = g_bc + c*DD + n0 + tx*8;
    float bv[8];
    #pragma unroll
    for (int j = 0; j < 8; j++) bv[j] = bcp[j];

    #pragma unroll
    for (int i = 0; i < 8; i++) {
        int m = m0 + ty*8 + i;
        if (m >= MQ) break;
        int bb = m / CC, j = m % CC;
        size_t row = (size_t)bb * NP + c * CC + j;
        float*       op = y + row*DD + n0 + tx*8;
        const float* xp = x + row*DD + n0 + tx*8;
        #pragma unroll
        for (int jj = 0; jj < 8; jj += 4) {
            float4 xv = *(const float4*)(xp + jj);
            float4 v;
            v.x = acc[i][jj+0] + bv[jj+0] + xv.x;
            v.y = acc[i][jj+1] + bv[jj+1] + xv.y;
            v.z = acc[i][jj+2] + bv[jj+2] + xv.z;
            v.w = acc[i][jj+3] + bv[jj+3] + xv.w;
            *(float4*)(op + jj) = v;
        }
    }
}

// ---------------- launch -------------------------------------------------------
extern "C" void kernel_launch(void* const* d_in, const int* in_sizes, int n_in,
                              void* d_out, int out_size) {
    const float* x      = (const float*)d_in[0];
    const float* w_in   = (const float*)d_in[1];
    const float* b_in   = (const float*)d_in[2];
    const float* w_out  = (const float*)d_in[3];
    const float* b_out  = (const float*)d_in[4];
    const float* w_fuse = (const float*)d_in[5];
    const float* b_fuse = (const float*)d_in[6];
    float* y = (float*)d_out;

    cudaFuncSetAttribute(gemm_kv_mma, cudaFuncAttributeMaxDynamicSharedMemorySize, KV_SMEM);
    cudaFuncSetAttribute(gemm_q_mma,  cudaFuncAttributeMaxDynamicSharedMemorySize, Q_SMEM);

    // launch order: gemm_kv at slot 4 -> profiled by ncu capture window
    split_all<<<(N4X + N4W + 255)/256, 256>>>(x, w_in);                     // 1

    gemm_q_mma<<<dim3(5, 38), 256, Q_SMEM>>>(b_in);                         // 2

    dim3 gc(2, 2, CC);
    gemm_comb<<<gc, 256>>>(w_fuse, w_out);                                  // 3

    dim3 gkv((MX + 127) / 128, NTOT / 128);   // (91, 76)
    gemm_kv_mma<<<gkv, 256, KV_SMEM>>>(b_in);                               // 4 (profiled)

    bias_comb<<<dim3(CC, DD/8), 256>>>(w_fuse, b_out, b_fuse);              // 5

    attn_kernel<<<dim3(HH, CC*BB), 256>>>();                                // 6

    dim3 gq((MQ + 127) / 128, 2, CC);
    out_fuse<<<gq, 256>>>(x, y);                                            // 7
}

// round 15
// speedup vs baseline: 1.0271x; 1.0271x over previous
#include <cuda_runtime.h>
#include <cuda_bf16.h>
#include <cstdint>

#define CC 19
#define NP 361
#define DD 256
#define BB 32
#define HH 8
#define HDIM 32
#define MX (BB*NP)   // 11552
#define MQ (BB*CC)   // 608
#define NKV 512
#define NTOT (CC*NKV) // 9728

// ---------------- scratch (device globals: no allocations allowed) ----------
__device__ float g_KT[(size_t)CC*BB*DD*NP];  // K transposed: [c][b][e][pos]
__device__ float g_V [(size_t)CC*BB*NP*DD];  // [c][b][pos][e]
__device__ float g_Q [(size_t)CC*BB*CC*DD];  // [c][b][j][e]
__device__ float g_AO[(size_t)CC*BB*CC*DD];
__device__ float g_Mc[(size_t)CC*DD*DD];
__device__ float g_bc[(size_t)CC*DD];

// bf16 split operands for tensor-core GEMMs
__device__ __nv_bfloat16 g_xh[(size_t)MX*DD];
__device__ __nv_bfloat16 g_xl[(size_t)MX*DD];
__device__ __nv_bfloat16 g_wh[(size_t)CC*768*DD];
__device__ __nv_bfloat16 g_wl[(size_t)CC*768*DD];

// ---------------- fused fp32 -> bf16 hi/lo split (x and w_in in one launch) ----
#define N4X ((MX*DD)/4)
#define N4W ((CC*768*DD)/4)
__global__ void split_all(const float* __restrict__ x, const float* __restrict__ w) {
    int i = blockIdx.x * 256 + threadIdx.x;
    const float* src;
    __nv_bfloat16 *h, *l;
    int idx;
    if (i < N4X) { src = x; h = g_xh; l = g_xl; idx = i; }
    else if (i < N4X + N4W) { src = w; h = g_wh; l = g_wl; idx = i - N4X; }
    else return;
    float4 v = ((const float4*)src)[idx];
    __nv_bfloat16 h0 = __float2bfloat16(v.x);
    __nv_bfloat16 h1 = __float2bfloat16(v.y);
    __nv_bfloat16 h2 = __float2bfloat16(v.z);
    __nv_bfloat16 h3 = __float2bfloat16(v.w);
    __nv_bfloat162 hh0 = {h0, h1}, hh1 = {h2, h3};
    __nv_bfloat162 ll0 = {__float2bfloat16(v.x - __bfloat162float(h0)),
                          __float2bfloat16(v.y - __bfloat162float(h1))};
    __nv_bfloat162 ll1 = {__float2bfloat16(v.z - __bfloat162float(h2)),
                          __float2bfloat16(v.w - __bfloat162float(h3))};
    ((__nv_bfloat162*)h)[idx*2+0] = hh0;
    ((__nv_bfloat162*)h)[idx*2+1] = hh1;
    ((__nv_bfloat162*)l)[idx*2+0] = ll0;
    ((__nv_bfloat162*)l)[idx*2+1] = ll1;
}

// ---------------- HMMA helpers -------------------------------------------------
__device__ __forceinline__ void mma16816(float* d, const uint32_t* a, const uint32_t* b) {
    asm volatile(
        "mma.sync.aligned.m16n8k16.row.col.f32.bf16.bf16.f32 "
        "{%0,%1,%2,%3}, {%4,%5,%6,%7}, {%8,%9}, {%0,%1,%2,%3};"
        : "+f"(d[0]), "+f"(d[1]), "+f"(d[2]), "+f"(d[3])
        : "r"(a[0]), "r"(a[1]), "r"(a[2]), "r"(a[3]), "r"(b[0]), "r"(b[1]));
}
__device__ __forceinline__ void ldsm4(uint32_t* r, uint32_t addr) {
    asm volatile("ldmatrix.sync.aligned.m8n8.x4.shared.b16 {%0,%1,%2,%3}, [%4];"
                 : "=r"(r[0]), "=r"(r[1]), "=r"(r[2]), "=r"(r[3]) : "r"(addr));
}
__device__ __forceinline__ void cp16(uint32_t saddr, const void* g) {
    asm volatile("cp.async.cg.shared.global [%0], [%1], 16;\n" :: "r"(saddr), "l"(g));
}
__device__ __forceinline__ uint32_t smem_u32(const void* p) {
    uint32_t a;
    asm("{ .reg .u64 t; cvta.to.shared.u64 t, %1; cvt.u32.u64 %0, t; }" : "=r"(a) : "l"(p));
    return a;
}

// ---------------- bf16x3 tensor-core KV GEMM (3-stage, 2 CTAs/SM) --------------
#define ROWB 48
#define ARRB (128*ROWB)
#define STGB (4*ARRB)
#define KV_SMEM (3*STGB)              // 73728 B

__global__ __launch_bounds__(256, 2)
void gemm_kv_mma(const float* __restrict__ b_in) {
    extern __shared__ char smraw[];
    const uint32_t sbase = smem_u32(smraw);

    const int tid  = threadIdx.x;
    const int warp = tid >> 5, lane = tid & 31;
    const int m0   = blockIdx.x * 128;
    const int n0g  = blockIdx.y * 128;
    const int c    = n0g / NKV;
    const int e0   = n0g % NKV;

    const int wm = (warp >> 2) * 64;
    const int wn = (warp & 3) * 32;

    uint32_t aoff[4], boff[2];
    {
        int mr = (lane & 7) + ((lane >> 3) & 1) * 8;
        int kb = (lane >> 4) * 16;
        #pragma unroll
        for (int ms = 0; ms < 4; ms++) aoff[ms] = (uint32_t)((wm + ms*16 + mr) * ROWB + kb);
        int nr  = (lane & 7) + ((lane >> 4) & 1) * 8;
        int kbb = ((lane >> 3) & 1) * 16;
        #pragma unroll
        for (int n2 = 0; n2 < 2; n2++) boff[n2] = (uint32_t)((wn + n2*16 + nr) * ROWB + kbb);
    }

    const int lrow = tid >> 1;
    const int lchk = tid & 1;
    int am = m0 + lrow; if (am > MX-1) am = MX-1;
    const __nv_bfloat16* pxh = g_xh + (size_t)am * DD + lchk*8;
    const __nv_bfloat16* pxl = g_xl + (size_t)am * DD + lchk*8;
    const size_t wrow = ((size_t)c * 768 + 256 + e0 + lrow) * DD + lchk*8;
    const __nv_bfloat16* pwh = g_wh + wrow;
    const __nv_bfloat16* pwl = g_wl + wrow;
    const uint32_t so = (uint32_t)(lrow*ROWB + lchk*16);

    auto issue = [&](int kt) {
        uint32_t s0 = sbase + (uint32_t)(kt % 3) * STGB + so;
        int k0 = kt * 16;
        cp16(s0 + 0*ARRB, pxh + k0);
        cp16(s0 + 1*ARRB, pxl + k0);
        cp16(s0 + 2*ARRB, pwh + k0);
        cp16(s0 + 3*ARRB, pwl + k0);
        asm volatile("cp.async.commit_group;");
    };

    uint32_t ah[2][4][4], al[2][4][4], bh[2][4][2], bl[2][4][2];
    auto ldfrags = [&](int buf, uint32_t base) {
        #pragma unroll
        for (int ms = 0; ms < 4; ms++) {
            ldsm4(ah[buf][ms], base + 0*ARRB + aoff[ms]);
            ldsm4(al[buf][ms], base + 1*ARRB + aoff[ms]);
        }
        #pragma unroll
        for (int n2 = 0; n2 < 2; n2++) {
            ldsm4(&bh[buf][n2*2][0], base + 2*ARRB + boff[n2]);
            ldsm4(&bl[buf][n2*2][0], base + 3*ARRB + boff[n2]);
        }
    };

    float acc[4][4][4];
    #pragma unroll
    for (int i = 0; i < 4; i++)
        #pragma unroll
        for (int j = 0; j < 4; j++)
            #pragma unroll
            for (int k = 0; k < 4; k++) acc[i][j][k] = 0.f;

    issue(0); issue(1); issue(2);
    asm volatile("cp.async.wait_group 2;");
    __syncthreads();
    ldfrags(0, sbase + 0*STGB);

    #pragma unroll
    for (int kt = 0; kt < 16; kt++) {
        const int cur = kt & 1, nxt = cur ^ 1;
        if (kt < 14)       asm volatile("cp.async.wait_group 1;");
        else if (kt == 14) asm volatile("cp.async.wait_group 0;");
        __syncthreads();
        if (kt + 3 < 16) issue(kt + 3);
        if (kt + 1 < 16) ldfrags(nxt, sbase + (uint32_t)((kt+1)%3)*STGB);

        #pragma unroll
        for (int ms = 0; ms < 4; ms++)
            #pragma unroll
            for (int ns = 0; ns < 4; ns++) {
                mma16816(acc[ms][ns], ah[cur][ms], bh[cur][ns]);
                mma16816(acc[ms][ns], ah[cur][ms], bl[cur][ns]);
                mma16816(acc[ms][ns], al[cur][ms], bh[cur][ns]);
            }
    }

    // epilogue: +bias; K goes out transposed ([e][pos]), V normal ([pos][e])
    const int qr = lane >> 2, qc = lane & 3;
    #pragma unroll
    for (int ns = 0; ns < 4; ns++) {
        int e = e0 + wn + ns*8 + qc*2;
        float b0 = b_in[c*768 + 256 + e];
        float b1 = b_in[c*768 + 256 + e + 1];
        bool isK = (e < 256);
        int col = isK ? e : e - 256;
        #pragma unroll
        for (int ms = 0; ms < 4; ms++) {
            int gm0 = m0 + wm + ms*16 + qr;
            #pragma unroll
            for (int half = 0; half < 2; half++) {
                int gm = gm0 + half*8;
                if (gm >= MX) continue;
                int bb = gm / NP, pos = gm % NP;
                float vx = acc[ms][ns][half*2+0] + b0;
                float vy = acc[ms][ns][half*2+1] + b1;
                size_t cb = (size_t)c*BB + bb;
                if (isK) {
                    g_KT[(cb*DD + col    )*NP + pos] = vx;
                    g_KT[(cb*DD + col + 1)*NP + pos] = vy;
                } else {
                    float2 v; v.x = vx; v.y = vy;
                    *(float2*)(g_V + (cb*NP + pos)*DD + col) = v;
                }
            }
        }
    }
}

// ---------------- Q projection GEMM (bf16x3 HMMA, gathered A rows, 3-stage) -----
__global__ __launch_bounds__(256, 2)
void gemm_q_mma(const float* __restrict__ b_in) {
    extern __shared__ char smraw[];
    const uint32_t sbase = smem_u32(smraw);

    const int tid  = threadIdx.x;
    const int warp = tid >> 5, lane = tid & 31;
    const int m0   = blockIdx.x * 128;
    const int c    = blockIdx.y >> 1;
    const int e0   = (blockIdx.y & 1) * 128;

    const int wm = (warp >> 2) * 64;
    const int wn = (warp & 3) * 32;

    uint32_t aoff[4], boff[2];
    {
        int mr = (lane & 7) + ((lane >> 3) & 1) * 8;
        int kb = (lane >> 4) * 16;
        #pragma unroll
        for (int ms = 0; ms < 4; ms++) aoff[ms] = (uint32_t)((wm + ms*16 + mr) * ROWB + kb);
        int nr  = (lane & 7) + ((lane >> 4) & 1) * 8;
        int kbb = ((lane >> 3) & 1) * 16;
        #pragma unroll
        for (int n2 = 0; n2 < 2; n2++) boff[n2] = (uint32_t)((wn + n2*16 + nr) * ROWB + kbb);
    }

    const int lrow = tid >> 1;
    const int lchk = tid & 1;
    int am = m0 + lrow; if (am > MQ-1) am = MQ-1;
    int xrow = (am / CC) * NP + c * CC + (am % CC);
    const __nv_bfloat16* pxh = g_xh + (size_t)xrow * DD + lchk*8;
    const __nv_bfloat16* pxl = g_xl + (size_t)xrow * DD + lchk*8;
    const size_t wrow = ((size_t)c * 768 + e0 + lrow) * DD + lchk*8;
    const __nv_bfloat16* pwh = g_wh + wrow;
    const __nv_bfloat16* pwl = g_wl + wrow;
    const uint32_t so = (uint32_t)(lrow*ROWB + lchk*16);

    auto issue = [&](int kt) {
        uint32_t s0 = sbase + (uint32_t)(kt % 3) * STGB + so;
        int k0 = kt * 16;
        cp16(s0 + 0*ARRB, pxh + k0);
        cp16(s0 + 1*ARRB, pxl + k0);
        cp16(s0 + 2*ARRB, pwh + k0);
        cp16(s0 + 3*ARRB, pwl + k0);
        asm volatile("cp.async.commit_group;");
    };

    uint32_t ah[2][4][4], al[2][4][4], bh[2][4][2], bl[2][4][2];
    auto ldfrags = [&](int buf, uint32_t base) {
        #pragma unroll
        for (int ms = 0; ms < 4; ms++) {
            ldsm4(ah[buf][ms], base + 0*ARRB + aoff[ms]);
            ldsm4(al[buf][ms], base + 1*ARRB + aoff[ms]);
        }
        #pragma unroll
        for (int n2 = 0; n2 < 2; n2++) {
            ldsm4(&bh[buf][n2*2][0], base + 2*ARRB + boff[n2]);
            ldsm4(&bl[buf][n2*2][0], base + 3*ARRB + boff[n2]);
        }
    };

    float acc[4][4][4];
    #pragma unroll
    for (int i = 0; i < 4; i++)
        #pragma unroll
        for (int j = 0; j < 4; j++)
            #pragma unroll
            for (int k = 0; k < 4; k++) acc[i][j][k] = 0.f;

    issue(0); issue(1); issue(2);
    asm volatile("cp.async.wait_group 2;");
    __syncthreads();
    ldfrags(0, sbase + 0*STGB);

    #pragma unroll
    for (int kt = 0; kt < 16; kt++) {
        const int cur = kt & 1, nxt = cur ^ 1;
        if (kt < 14)       asm volatile("cp.async.wait_group 1;");
        else if (kt == 14) asm volatile("cp.async.wait_group 0;");
        __syncthreads();
        if (kt + 3 < 16) issue(kt + 3);
        if (kt + 1 < 16) ldfrags(nxt, sbase + (uint32_t)((kt+1)%3)*STGB);

        #pragma unroll
        for (int ms = 0; ms < 4; ms++)
            #pragma unroll
            for (int ns = 0; ns < 4; ns++) {
                mma16816(acc[ms][ns], ah[cur][ms], bh[cur][ns]);
                mma16816(acc[ms][ns], ah[cur][ms], bl[cur][ns]);
                mma16816(acc[ms][ns], al[cur][ms], bh[cur][ns]);
            }
    }

    const int qr = lane >> 2, qc = lane & 3;
    #pragma unroll
    for (int ns = 0; ns < 4; ns++) {
        int e = e0 + wn + ns*8 + qc*2;
        float b0 = b_in[c*768 + e];
        float b1 = b_in[c*768 + e + 1];
        #pragma unroll
        for (int ms = 0; ms < 4; ms++) {
            int gm0 = m0 + wm + ms*16 + qr;
            #pragma unroll
            for (int half = 0; half < 2; half++) {
                int gm = gm0 + half*8;
                if (gm >= MQ) continue;
                float2 v;
                v.x = acc[ms][ns][half*2+0] + b0;
                v.y = acc[ms][ns][half*2+1] + b1;
                *(float2*)(g_Q + ((size_t)c*MQ + gm)*DD + e) = v;
            }
        }
    }
}

// ---------------- combined weight Mc[c] = w_fuse @ w_out[c], 64x64 tiles -------
// grid (4, 4, 19) = 304 CTAs, 256 threads (16x16), 4x4 per thread, k-tile 16
__global__ __launch_bounds__(256)
void gemm_comb64(const float* __restrict__ w_fuse, const float* __restrict__ w_out) {
    const int c  = blockIdx.z;
    const int m0 = blockIdx.x * 64;
    const int n0 = blockIdx.y * 64;
    __shared__ float As[16][68];   // [k][m]
    __shared__ float Bs[16][68];   // [k][n]
    const int tid = threadIdx.x;
    const int ty  = tid >> 4, tx = tid & 15;

    // loaders: A tile 64 rows x 16 k (w_fuse[m][k]); B tile 16 k x 64 n (w_out[k][n])
    const int aRow = tid >> 2, aCol = (tid & 3) << 2;   // 64 rows x 4-chunk of 16
    const int bK   = tid >> 4, bN   = (tid & 15) << 2;  // 16 k x 4-chunk of 64

    const float* Ap = w_fuse + (size_t)(m0 + aRow) * DD + aCol;
    const float* Bbase = w_out + (size_t)c * DD * DD;

    float acc[4][4];
    #pragma unroll
    for (int i = 0; i < 4; i++)
        #pragma unroll
        for (int j = 0; j < 4; j++) acc[i][j] = 0.f;

    for (int kt = 0; kt < DD; kt += 16) {
        float4 a = *(const float4*)(Ap + kt);
        float4 b = *(const float4*)(Bbase + (size_t)(kt + bK) * DD + n0 + bN);
        As[aCol+0][aRow]=a.x; As[aCol+1][aRow]=a.y;
        As[aCol+2][aRow]=a.z; As[aCol+3][aRow]=a.w;
        *(float4*)&Bs[bK][bN] = b;
        __syncthreads();
        #pragma unroll
        for (int k = 0; k < 16; k++) {
            float ra[4], rb[4];
            *(float4*)ra = *(const float4*)&As[k][ty*4];
            *(float4*)rb = *(const float4*)&Bs[k][tx*4];
            #pragma unroll
            for (int i = 0; i < 4; i++)
                #pragma unroll
                for (int j = 0; j < 4; j++)
                    acc[i][j] = fmaf(ra[i], rb[j], acc[i][j]);
        }
        __syncthreads();
    }

    #pragma unroll
    for (int i = 0; i < 4; i++) {
        float* op = g_Mc + ((size_t)c*DD + m0 + ty*4 + i)*DD + n0 + tx*4;
        float4 v; v.x=acc[i][0]; v.y=acc[i][1]; v.z=acc[i][2]; v.w=acc[i][3];
        *(float4*)op = v;
    }
}

// ---------------- combined bias (warp per output) ------------------------------
__global__ void bias_comb(const float* __restrict__ w_fuse,
                          const float* __restrict__ b_out,
                          const float* __restrict__ b_fuse) {
    int c = blockIdx.x;
    int e = blockIdx.y * 8 + (threadIdx.x >> 5);
    int lane = threadIdx.x & 31;
    const float* wf = w_fuse + (size_t)e * DD;
    const float* bo = b_out + c * DD;
    float s = 0.f;
    #pragma unroll
    for (int i = 0; i < 8; i++) s = fmaf(wf[lane + i*32], bo[lane + i*32], s);
    #pragma unroll
    for (int o = 16; o; o >>= 1) s += __shfl_xor_sync(~0u, s, o);
    if (lane == 0) g_bc[c*DD + e] = s + b_fuse[e];
}

// ---------------- attention: one CTA per (h, c, b), coalesced KT reads ---------
__global__ __launch_bounds__(256)
void attn_kernel() {
    __shared__ float S[24][368];     // 35328 B (rows 19..23 = zero pad for PV)
    __shared__ float Qh[CC][36];     // 2736 B
    const int h  = blockIdx.x;
    const int cb = blockIdx.y;       // c*BB + b
    const int c  = cb / BB;
    const int hoff = h * HDIM;
    const int tid  = threadIdx.x;
    const int wid  = tid >> 5, lane = tid & 31;

    const float* KTg = g_KT + ((size_t)cb * DD + hoff) * NP;  // [d][pos]
    const float* Vg  = g_V  + (size_t)cb * NP * DD;
    const float* Qg  = g_Q  + (size_t)cb * CC * DD;
    float*       Og  = g_AO + (size_t)cb * CC * DD;

    // stage Q head-slice (19x32) + zero pad rows of S
    for (int i = tid; i < CC*8; i += 256) {
        int row = i >> 3, q4 = i & 7;
        float4 v = *(const float4*)(Qg + (size_t)row * DD + hoff + q4*4);
        *(float4*)&Qh[row][q4*4] = v;
    }
    for (int i = tid; i < 5*368; i += 256) (&S[19][0])[i] = 0.f;
    __syncthreads();

    const float scale = 0.17677669529663687f;   // 1/sqrt(32)

    // ---- scores + mask (coalesced KT: lane=k, stride-NP per dim) ----
    for (int k = tid; k < NP; k += 256) {
        float kr[HDIM];
        #pragma unroll
        for (int d = 0; d < HDIM; d++) kr[d] = KTg[(size_t)d * NP + k];
        int ki = k / CC, kj = k - ki*CC;
        for (int j = 0; j < CC; j++) {
            const float4* qp = (const float4*)&Qh[j][0];
            float s0 = 0.f, s1 = 0.f, s2 = 0.f, s3 = 0.f;
            #pragma unroll
            for (int q = 0; q < 8; q++) {
                float4 qv = qp[q];
                s0 = fmaf(kr[q*4+0], qv.x, s0);
                s1 = fmaf(kr[q*4+1], qv.y, s1);
                s2 = fmaf(kr[q*4+2], qv.z, s2);
                s3 = fmaf(kr[q*4+3], qv.w, s3);
            }
            float s = (s0 + s1) + (s2 + s3);
            bool ok = (ki == c) | (kj == c) | (ki == j) | (kj == j);
            S[j][k] = ok ? s * scale : -1e30f;
        }
    }
    __syncthreads();

    // ---- softmax, one warp per row ----
    for (int j = wid; j < CC; j += 8) {
        float mx = -1e30f;
        for (int k = lane; k < NP; k += 32) mx = fmaxf(mx, S[j][k]);
        #pragma unroll
        for (int o = 16; o; o >>= 1) mx = fmaxf(mx, __shfl_xor_sync(~0u, mx, o));
        float sum = 0.f;
        for (int k = lane; k < NP; k += 32) {
            float e = __expf(S[j][k] - mx);
            S[j][k] = e; sum += e;
        }
        #pragma unroll
        for (int o = 16; o; o >>= 1) sum += __shfl_xor_sync(~0u, sum, o);
        float inv = 1.f / sum;
        for (int k = lane; k < NP; k += 32) S[j][k] *= inv;
    }
    __syncthreads();

    // ---- P @ V (coalesced global V, x4 unroll, branchless via pad rows) ----
    {
        const int d = lane, jg = wid;
        const float* vp = Vg + hoff + d;
        float o0 = 0.f, o1 = 0.f, o2 = 0.f;
        for (int k = 0; k < 360; k += 4) {
            float v0 = vp[(size_t)(k+0) * DD];
            float v1 = vp[(size_t)(k+1) * DD];
            float v2 = vp[(size_t)(k+2) * DD];
            float v3 = vp[(size_t)(k+3) * DD];
            float4 sA = *(const float4*)&S[jg   ][k];
            float4 sB = *(const float4*)&S[jg+8 ][k];
            float4 sC = *(const float4*)&S[jg+16][k];
            o0 = fmaf(sA.x, v0, o0); o1 = fmaf(sB.x, v0, o1); o2 = fmaf(sC.x, v0, o2);
            o0 = fmaf(sA.y, v1, o0); o1 = fmaf(sB.y, v1, o1); o2 = fmaf(sC.y, v1, o2);
            o0 = fmaf(sA.z, v2, o0); o1 = fmaf(sB.z, v2, o1); o2 = fmaf(sC.z, v2, o2);
            o0 = fmaf(sA.w, v3, o0); o1 = fmaf(sB.w, v3, o1); o2 = fmaf(sC.w, v3, o2);
        }
        {   // tail k = 360
            float v = vp[(size_t)360 * DD];
            o0 = fmaf(S[jg   ][360], v, o0);
            o1 = fmaf(S[jg+8 ][360], v, o1);
            o2 = fmaf(S[jg+16][360], v, o2);
        }
        Og[jg*DD + hoff + d]     = o0;
        Og[(jg+8)*DD + hoff + d] = o1;
        if (jg + 16 < CC) Og[(jg+16)*DD + hoff + d] = o2;
    }
}

// ---------------- out-proj + fuse + residual ----------------------------------
__global__ __launch_bounds__(256, 2)
void out_fuse(const float* __restrict__ x, float* __restrict__ y) {
    const int c  = blockIdx.z;
    const int m0 = blockIdx.x * 128;
    const int n0 = blockIdx.y * 128;
    __shared__ float As[8][128];
    __shared__ float Bs[8][128];
    const int tid   = threadIdx.x;
    const int ldRow = tid >> 1;
    const int ldCol = (tid & 1) << 2;

    int am = m0 + ldRow; if (am > MQ - 1) am = MQ - 1;
    const float* Ap = g_AO + ((size_t)c*MQ + am) * DD + ldCol;
    const float* Bp = g_Mc + ((size_t)c*DD + n0 + ldRow) * DD + ldCol;

    const int ty = tid >> 4, tx = tid & 15;
    float acc[8][8];
    #pragma unroll
    for (int i = 0; i < 8; i++)
        #pragma unroll
        for (int j = 0; j < 8; j++) acc[i][j] = 0.f;

    for (int kt = 0; kt < DD; kt += 8) {
        float4 a = *(const float4*)(Ap + kt);
        float4 b = *(const float4*)(Bp + kt);
        As[ldCol+0][ldRow]=a.x; As[ldCol+1][ldRow]=a.y;
        As[ldCol+2][ldRow]=a.z; As[ldCol+3][ldRow]=a.w;
        Bs[ldCol+0][ldRow]=b.x; Bs[ldCol+1][ldRow]=b.y;
        Bs[ldCol+2][ldRow]=b.z; Bs[ldCol+3][ldRow]=b.w;
        __syncthreads();
        #pragma unroll
        for (int k = 0; k < 8; k++) {
            float ra[8], rb[8];
            *(float4*)&ra[0] = *(const float4*)&As[k][ty*8];
            *(float4*)&ra[4] = *(const float4*)&As[k][ty*8+4];
            *(float4*)&rb[0] = *(const float4*)&Bs[k][tx*8];
            *(float4*)&rb[4] = *(const float4*)&Bs[k][tx*8+4];
            #pragma unroll
            for (int i = 0; i < 8; i++)
                #pragma unroll
                for (int j = 0; j < 8; j++)
                    acc[i][j] = fmaf(ra[i], rb[j], acc[i][j]);
        }
        __syncthreads();
    }

    const float* bcp = g_bc + c*DD + n0 + tx*8;
    float bv[8];
    #pragma unroll
    for (int j = 0; j < 8; j++) bv[j] = bcp[j];

    #pragma unroll
    for (int i = 0; i < 8; i++) {
        int m = m0 + ty*8 + i;
        if (m >= MQ) break;
        int bb = m / CC, j = m % CC;
        size_t row = (size_t)bb * NP + c * CC + j;
        float*       op = y + row*DD + n0 + tx*8;
        const float* xp = x + row*DD + n0 + tx*8;
        #pragma unroll
        for (int jj = 0; jj < 8; jj += 4) {
            float4 xv = *(const float4*)(xp + jj);
            float4 v;
            v.x = acc[i][jj+0] + bv[jj+0] + xv.x;
            v.y = acc[i][jj+1] + bv[jj+1] + xv.y;
            v.z = acc[i][jj+2] + bv[jj+2] + xv.z;
            v.w = acc[i][jj+3] + bv[jj+3] + xv.w;
            *(float4*)(op + jj) = v;
        }
    }
}

// ---------------- launch -------------------------------------------------------
extern "C" void kernel_launch(void* const* d_in, const int* in_sizes, int n_in,
                              void* d_out, int out_size) {
    const float* x      = (const float*)d_in[0];
    const float* w_in   = (const float*)d_in[1];
    const float* b_in   = (const float*)d_in[2];
    const float* w_out  = (const float*)d_in[3];
    const float* b_out  = (const float*)d_in[4];
    const float* w_fuse = (const float*)d_in[5];
    const float* b_fuse = (const float*)d_in[6];
    float* y = (float*)d_out;

    cudaFuncSetAttribute(gemm_kv_mma, cudaFuncAttributeMaxDynamicSharedMemorySize, KV_SMEM);
    cudaFuncSetAttribute(gemm_q_mma,  cudaFuncAttributeMaxDynamicSharedMemorySize, KV_SMEM);

    // launch order: gemm_kv at slot 4 -> profiled by ncu capture window
    split_all<<<(N4X + N4W + 255)/256, 256>>>(x, w_in);                     // 1

    gemm_q_mma<<<dim3(5, 38), 256, KV_SMEM>>>(b_in);                        // 2

    gemm_comb64<<<dim3(4, 4, CC), 256>>>(w_fuse, w_out);                    // 3

    dim3 gkv((MX + 127) / 128, NTOT / 128);   // (91, 76)
    gemm_kv_mma<<<gkv, 256, KV_SMEM>>>(b_in);                               // 4 (profiled)

    bias_comb<<<dim3(CC, DD/8), 256>>>(w_fuse, b_out, b_fuse);              // 5

    attn_kernel<<<dim3(HH, CC*BB), 256>>>();                                // 6

    dim3 gq((MQ + 127) / 128, 2, CC);
    out_fuse<<<gq, 256>>>(x, y);                                            // 7
}

// round 16
// speedup vs baseline: 1.0542x; 1.0264x over previous
#include <cuda_runtime.h>
#include <cuda_bf16.h>
#include <cstdint>

#define CC 19
#define NP 361
#define DD 256
#define BB 32
#define HH 8
#define HDIM 32
#define MX (BB*NP)   // 11552
#define MQ (BB*CC)   // 608
#define NKV 512
#define NTOT (CC*NKV) // 9728

// ---------------- scratch (device globals: no allocations allowed) ----------
__device__ float g_KT[(size_t)CC*BB*DD*NP];  // K transposed: [c][b][e][pos]
__device__ float g_V [(size_t)CC*BB*NP*DD];  // [c][b][pos][e]
__device__ float g_Q [(size_t)CC*BB*CC*DD];  // [c][b][j][e]
__device__ float g_AO[(size_t)CC*BB*CC*DD];
__device__ float g_Mc[(size_t)CC*DD*DD];
__device__ float g_bc[(size_t)CC*DD];

// bf16 split operands for tensor-core GEMMs
__device__ __nv_bfloat16 g_xh[(size_t)MX*DD];
__device__ __nv_bfloat16 g_xl[(size_t)MX*DD];
__device__ __nv_bfloat16 g_wh[(size_t)CC*768*DD];
__device__ __nv_bfloat16 g_wl[(size_t)CC*768*DD];

// ---------------- fused fp32 -> bf16 hi/lo split (x and w_in in one launch) ----
#define N4X ((MX*DD)/4)
#define N4W ((CC*768*DD)/4)
__global__ void split_all(const float* __restrict__ x, const float* __restrict__ w) {
    int i = blockIdx.x * 256 + threadIdx.x;
    const float* src;
    __nv_bfloat16 *h, *l;
    int idx;
    if (i < N4X) { src = x; h = g_xh; l = g_xl; idx = i; }
    else if (i < N4X + N4W) { src = w; h = g_wh; l = g_wl; idx = i - N4X; }
    else return;
    float4 v = ((const float4*)src)[idx];
    __nv_bfloat16 h0 = __float2bfloat16(v.x);
    __nv_bfloat16 h1 = __float2bfloat16(v.y);
    __nv_bfloat16 h2 = __float2bfloat16(v.z);
    __nv_bfloat16 h3 = __float2bfloat16(v.w);
    __nv_bfloat162 hh0 = {h0, h1}, hh1 = {h2, h3};
    __nv_bfloat162 ll0 = {__float2bfloat16(v.x - __bfloat162float(h0)),
                          __float2bfloat16(v.y - __bfloat162float(h1))};
    __nv_bfloat162 ll1 = {__float2bfloat16(v.z - __bfloat162float(h2)),
                          __float2bfloat16(v.w - __bfloat162float(h3))};
    ((__nv_bfloat162*)h)[idx*2+0] = hh0;
    ((__nv_bfloat162*)h)[idx*2+1] = hh1;
    ((__nv_bfloat162*)l)[idx*2+0] = ll0;
    ((__nv_bfloat162*)l)[idx*2+1] = ll1;
}

// ---------------- HMMA helpers -------------------------------------------------
__device__ __forceinline__ void mma16816(float* d, const uint32_t* a, const uint32_t* b) {
    asm volatile(
        "mma.sync.aligned.m16n8k16.row.col.f32.bf16.bf16.f32 "
        "{%0,%1,%2,%3}, {%4,%5,%6,%7}, {%8,%9}, {%0,%1,%2,%3};"
        : "+f"(d[0]), "+f"(d[1]), "+f"(d[2]), "+f"(d[3])
        : "r"(a[0]), "r"(a[1]), "r"(a[2]), "r"(a[3]), "r"(b[0]), "r"(b[1]));
}
__device__ __forceinline__ void ldsm4(uint32_t* r, uint32_t addr) {
    asm volatile("ldmatrix.sync.aligned.m8n8.x4.shared.b16 {%0,%1,%2,%3}, [%4];"
                 : "=r"(r[0]), "=r"(r[1]), "=r"(r[2]), "=r"(r[3]) : "r"(addr));
}
__device__ __forceinline__ void cp16(uint32_t saddr, const void* g) {
    asm volatile("cp.async.cg.shared.global [%0], [%1], 16;\n" :: "r"(saddr), "l"(g));
}
__device__ __forceinline__ uint32_t smem_u32(const void* p) {
    uint32_t a;
    asm("{ .reg .u64 t; cvta.to.shared.u64 t, %1; cvt.u32.u64 %0, t; }" : "=r"(a) : "l"(p));
    return a;
}

// ---------------- bf16x3 tensor-core KV GEMM (3-stage, 2 CTAs/SM) --------------
#define ROWB 48
#define ARRB (128*ROWB)
#define STGB (4*ARRB)
#define KV_SMEM (3*STGB)              // 73728 B

__global__ __launch_bounds__(256, 2)
void gemm_kv_mma(const float* __restrict__ b_in) {
    extern __shared__ char smraw[];
    const uint32_t sbase = smem_u32(smraw);

    const int tid  = threadIdx.x;
    const int warp = tid >> 5, lane = tid & 31;
    const int m0   = blockIdx.x * 128;
    const int n0g  = blockIdx.y * 128;
    const int c    = n0g / NKV;
    const int e0   = n0g % NKV;

    const int wm = (warp >> 2) * 64;
    const int wn = (warp & 3) * 32;

    uint32_t aoff[4], boff[2];
    {
        int mr = (lane & 7) + ((lane >> 3) & 1) * 8;
        int kb = (lane >> 4) * 16;
        #pragma unroll
        for (int ms = 0; ms < 4; ms++) aoff[ms] = (uint32_t)((wm + ms*16 + mr) * ROWB + kb);
        int nr  = (lane & 7) + ((lane >> 4) & 1) * 8;
        int kbb = ((lane >> 3) & 1) * 16;
        #pragma unroll
        for (int n2 = 0; n2 < 2; n2++) boff[n2] = (uint32_t)((wn + n2*16 + nr) * ROWB + kbb);
    }

    const int lrow = tid >> 1;
    const int lchk = tid & 1;
    int am = m0 + lrow; if (am > MX-1) am = MX-1;
    const __nv_bfloat16* pxh = g_xh + (size_t)am * DD + lchk*8;
    const __nv_bfloat16* pxl = g_xl + (size_t)am * DD + lchk*8;
    const size_t wrow = ((size_t)c * 768 + 256 + e0 + lrow) * DD + lchk*8;
    const __nv_bfloat16* pwh = g_wh + wrow;
    const __nv_bfloat16* pwl = g_wl + wrow;
    const uint32_t so = (uint32_t)(lrow*ROWB + lchk*16);

    auto issue = [&](int kt) {
        uint32_t s0 = sbase + (uint32_t)(kt % 3) * STGB + so;
        int k0 = kt * 16;
        cp16(s0 + 0*ARRB, pxh + k0);
        cp16(s0 + 1*ARRB, pxl + k0);
        cp16(s0 + 2*ARRB, pwh + k0);
        cp16(s0 + 3*ARRB, pwl + k0);
        asm volatile("cp.async.commit_group;");
    };

    uint32_t ah[2][4][4], al[2][4][4], bh[2][4][2], bl[2][4][2];
    auto ldfrags = [&](int buf, uint32_t base) {
        #pragma unroll
        for (int ms = 0; ms < 4; ms++) {
            ldsm4(ah[buf][ms], base + 0*ARRB + aoff[ms]);
            ldsm4(al[buf][ms], base + 1*ARRB + aoff[ms]);
        }
        #pragma unroll
        for (int n2 = 0; n2 < 2; n2++) {
            ldsm4(&bh[buf][n2*2][0], base + 2*ARRB + boff[n2]);
            ldsm4(&bl[buf][n2*2][0], base + 3*ARRB + boff[n2]);
        }
    };

    float acc[4][4][4];
    #pragma unroll
    for (int i = 0; i < 4; i++)
        #pragma unroll
        for (int j = 0; j < 4; j++)
            #pragma unroll
            for (int k = 0; k < 4; k++) acc[i][j][k] = 0.f;

    issue(0); issue(1); issue(2);
    asm volatile("cp.async.wait_group 2;");
    __syncthreads();
    ldfrags(0, sbase + 0*STGB);

    #pragma unroll
    for (int kt = 0; kt < 16; kt++) {
        const int cur = kt & 1, nxt = cur ^ 1;
        if (kt < 14)       asm volatile("cp.async.wait_group 1;");
        else if (kt == 14) asm volatile("cp.async.wait_group 0;");
        __syncthreads();
        if (kt + 3 < 16) issue(kt + 3);
        if (kt + 1 < 16) ldfrags(nxt, sbase + (uint32_t)((kt+1)%3)*STGB);

        #pragma unroll
        for (int ms = 0; ms < 4; ms++)
            #pragma unroll
            for (int ns = 0; ns < 4; ns++) {
                mma16816(acc[ms][ns], ah[cur][ms], bh[cur][ns]);
                mma16816(acc[ms][ns], ah[cur][ms], bl[cur][ns]);
                mma16816(acc[ms][ns], al[cur][ms], bh[cur][ns]);
            }
    }

    // epilogue: +bias; K goes out transposed ([e][pos]), V normal ([pos][e])
    const int qr = lane >> 2, qc = lane & 3;
    #pragma unroll
    for (int ns = 0; ns < 4; ns++) {
        int e = e0 + wn + ns*8 + qc*2;
        float b0 = b_in[c*768 + 256 + e];
        float b1 = b_in[c*768 + 256 + e + 1];
        bool isK = (e < 256);
        int col = isK ? e : e - 256;
        #pragma unroll
        for (int ms = 0; ms < 4; ms++) {
            int gm0 = m0 + wm + ms*16 + qr;
            #pragma unroll
            for (int half = 0; half < 2; half++) {
                int gm = gm0 + half*8;
                if (gm >= MX) continue;
                int bb = gm / NP, pos = gm % NP;
                float vx = acc[ms][ns][half*2+0] + b0;
                float vy = acc[ms][ns][half*2+1] + b1;
                size_t cb = (size_t)c*BB + bb;
                if (isK) {
                    g_KT[(cb*DD + col    )*NP + pos] = vx;
                    g_KT[(cb*DD + col + 1)*NP + pos] = vy;
                } else {
                    float2 v; v.x = vx; v.y = vy;
                    *(float2*)(g_V + (cb*NP + pos)*DD + col) = v;
                }
            }
        }
    }
}

// ---------------- Q projection GEMM (bf16x3 HMMA, gathered A rows, 3-stage) -----
__global__ __launch_bounds__(256, 2)
void gemm_q_mma(const float* __restrict__ b_in) {
    extern __shared__ char smraw[];
    const uint32_t sbase = smem_u32(smraw);

    const int tid  = threadIdx.x;
    const int warp = tid >> 5, lane = tid & 31;
    const int m0   = blockIdx.x * 128;
    const int c    = blockIdx.y >> 1;
    const int e0   = (blockIdx.y & 1) * 128;

    const int wm = (warp >> 2) * 64;
    const int wn = (warp & 3) * 32;

    uint32_t aoff[4], boff[2];
    {
        int mr = (lane & 7) + ((lane >> 3) & 1) * 8;
        int kb = (lane >> 4) * 16;
        #pragma unroll
        for (int ms = 0; ms < 4; ms++) aoff[ms] = (uint32_t)((wm + ms*16 + mr) * ROWB + kb);
        int nr  = (lane & 7) + ((lane >> 4) & 1) * 8;
        int kbb = ((lane >> 3) & 1) * 16;
        #pragma unroll
        for (int n2 = 0; n2 < 2; n2++) boff[n2] = (uint32_t)((wn + n2*16 + nr) * ROWB + kbb);
    }

    const int lrow = tid >> 1;
    const int lchk = tid & 1;
    int am = m0 + lrow; if (am > MQ-1) am = MQ-1;
    int xrow = (am / CC) * NP + c * CC + (am % CC);
    const __nv_bfloat16* pxh = g_xh + (size_t)xrow * DD + lchk*8;
    const __nv_bfloat16* pxl = g_xl + (size_t)xrow * DD + lchk*8;
    const size_t wrow = ((size_t)c * 768 + e0 + lrow) * DD + lchk*8;
    const __nv_bfloat16* pwh = g_wh + wrow;
    const __nv_bfloat16* pwl = g_wl + wrow;
    const uint32_t so = (uint32_t)(lrow*ROWB + lchk*16);

    auto issue = [&](int kt) {
        uint32_t s0 = sbase + (uint32_t)(kt % 3) * STGB + so;
        int k0 = kt * 16;
        cp16(s0 + 0*ARRB, pxh + k0);
        cp16(s0 + 1*ARRB, pxl + k0);
        cp16(s0 + 2*ARRB, pwh + k0);
        cp16(s0 + 3*ARRB, pwl + k0);
        asm volatile("cp.async.commit_group;");
    };

    uint32_t ah[2][4][4], al[2][4][4], bh[2][4][2], bl[2][4][2];
    auto ldfrags = [&](int buf, uint32_t base) {
        #pragma unroll
        for (int ms = 0; ms < 4; ms++) {
            ldsm4(ah[buf][ms], base + 0*ARRB + aoff[ms]);
            ldsm4(al[buf][ms], base + 1*ARRB + aoff[ms]);
        }
        #pragma unroll
        for (int n2 = 0; n2 < 2; n2++) {
            ldsm4(&bh[buf][n2*2][0], base + 2*ARRB + boff[n2]);
            ldsm4(&bl[buf][n2*2][0], base + 3*ARRB + boff[n2]);
        }
    };

    float acc[4][4][4];
    #pragma unroll
    for (int i = 0; i < 4; i++)
        #pragma unroll
        for (int j = 0; j < 4; j++)
            #pragma unroll
            for (int k = 0; k < 4; k++) acc[i][j][k] = 0.f;

    issue(0); issue(1); issue(2);
    asm volatile("cp.async.wait_group 2;");
    __syncthreads();
    ldfrags(0, sbase + 0*STGB);

    #pragma unroll
    for (int kt = 0; kt < 16; kt++) {
        const int cur = kt & 1, nxt = cur ^ 1;
        if (kt < 14)       asm volatile("cp.async.wait_group 1;");
        else if (kt == 14) asm volatile("cp.async.wait_group 0;");
        __syncthreads();
        if (kt + 3 < 16) issue(kt + 3);
        if (kt + 1 < 16) ldfrags(nxt, sbase + (uint32_t)((kt+1)%3)*STGB);

        #pragma unroll
        for (int ms = 0; ms < 4; ms++)
            #pragma unroll
            for (int ns = 0; ns < 4; ns++) {
                mma16816(acc[ms][ns], ah[cur][ms], bh[cur][ns]);
                mma16816(acc[ms][ns], ah[cur][ms], bl[cur][ns]);
                mma16816(acc[ms][ns], al[cur][ms], bh[cur][ns]);
            }
    }

    const int qr = lane >> 2, qc = lane & 3;
    #pragma unroll
    for (int ns = 0; ns < 4; ns++) {
        int e = e0 + wn + ns*8 + qc*2;
        float b0 = b_in[c*768 + e];
        float b1 = b_in[c*768 + e + 1];
        #pragma unroll
        for (int ms = 0; ms < 4; ms++) {
            int gm0 = m0 + wm + ms*16 + qr;
            #pragma unroll
            for (int half = 0; half < 2; half++) {
                int gm = gm0 + half*8;
                if (gm >= MQ) continue;
                float2 v;
                v.x = acc[ms][ns][half*2+0] + b0;
                v.y = acc[ms][ns][half*2+1] + b1;
                *(float2*)(g_Q + ((size_t)c*MQ + gm)*DD + e) = v;
            }
        }
    }
}

// ---------------- combined weight Mc[c] = w_fuse @ w_out[c], 64x64 tiles -------
__global__ __launch_bounds__(256)
void gemm_comb64(const float* __restrict__ w_fuse, const float* __restrict__ w_out) {
    const int c  = blockIdx.z;
    const int m0 = blockIdx.x * 64;
    const int n0 = blockIdx.y * 64;
    __shared__ float As[16][68];   // [k][m]
    __shared__ float Bs[16][68];   // [k][n]
    const int tid = threadIdx.x;
    const int ty  = tid >> 4, tx = tid & 15;

    const int aRow = tid >> 2, aCol = (tid & 3) << 2;
    const int bK   = tid >> 4, bN   = (tid & 15) << 2;

    const float* Ap = w_fuse + (size_t)(m0 + aRow) * DD + aCol;
    const float* Bbase = w_out + (size_t)c * DD * DD;

    float acc[4][4];
    #pragma unroll
    for (int i = 0; i < 4; i++)
        #pragma unroll
        for (int j = 0; j < 4; j++) acc[i][j] = 0.f;

    for (int kt = 0; kt < DD; kt += 16) {
        float4 a = *(const float4*)(Ap + kt);
        float4 b = *(const float4*)(Bbase + (size_t)(kt + bK) * DD + n0 + bN);
        As[aCol+0][aRow]=a.x; As[aCol+1][aRow]=a.y;
        As[aCol+2][aRow]=a.z; As[aCol+3][aRow]=a.w;
        *(float4*)&Bs[bK][bN] = b;
        __syncthreads();
        #pragma unroll
        for (int k = 0; k < 16; k++) {
            float ra[4], rb[4];
            *(float4*)ra = *(const float4*)&As[k][ty*4];
            *(float4*)rb = *(const float4*)&Bs[k][tx*4];
            #pragma unroll
            for (int i = 0; i < 4; i++)
                #pragma unroll
                for (int j = 0; j < 4; j++)
                    acc[i][j] = fmaf(ra[i], rb[j], acc[i][j]);
        }
        __syncthreads();
    }

    #pragma unroll
    for (int i = 0; i < 4; i++) {
        float* op = g_Mc + ((size_t)c*DD + m0 + ty*4 + i)*DD + n0 + tx*4;
        float4 v; v.x=acc[i][0]; v.y=acc[i][1]; v.z=acc[i][2]; v.w=acc[i][3];
        *(float4*)op = v;
    }
}

// ---------------- combined bias (warp per output) ------------------------------
__global__ void bias_comb(const float* __restrict__ w_fuse,
                          const float* __restrict__ b_out,
                          const float* __restrict__ b_fuse) {
    int c = blockIdx.x;
    int e = blockIdx.y * 8 + (threadIdx.x >> 5);
    int lane = threadIdx.x & 31;
    const float* wf = w_fuse + (size_t)e * DD;
    const float* bo = b_out + c * DD;
    float s = 0.f;
    #pragma unroll
    for (int i = 0; i < 8; i++) s = fmaf(wf[lane + i*32], bo[lane + i*32], s);
    #pragma unroll
    for (int o = 16; o; o >>= 1) s += __shfl_xor_sync(~0u, s, o);
    if (lane == 0) g_bc[c*DD + e] = s + b_fuse[e];
}

// ---------------- attention: one CTA per (h, c, b), coalesced KT reads ---------
__global__ __launch_bounds__(256)
void attn_kernel() {
    __shared__ float S[24][368];     // 35328 B (rows 19..23 = zero pad for PV)
    __shared__ float Qh[CC][36];     // 2736 B
    const int h  = blockIdx.x;
    const int cb = blockIdx.y;       // c*BB + b
    const int c  = cb / BB;
    const int hoff = h * HDIM;
    const int tid  = threadIdx.x;
    const int wid  = tid >> 5, lane = tid & 31;

    const float* KTg = g_KT + ((size_t)cb * DD + hoff) * NP;  // [d][pos]
    const float* Vg  = g_V  + (size_t)cb * NP * DD;
    const float* Qg  = g_Q  + (size_t)cb * CC * DD;
    float*       Og  = g_AO + (size_t)cb * CC * DD;

    // stage Q head-slice (19x32) + zero pad rows of S
    for (int i = tid; i < CC*8; i += 256) {
        int row = i >> 3, q4 = i & 7;
        float4 v = *(const float4*)(Qg + (size_t)row * DD + hoff + q4*4);
        *(float4*)&Qh[row][q4*4] = v;
    }
    for (int i = tid; i < 5*368; i += 256) (&S[19][0])[i] = 0.f;
    __syncthreads();

    const float scale = 0.17677669529663687f;   // 1/sqrt(32)

    // ---- scores + mask (coalesced KT: lane=k, stride-NP per dim) ----
    for (int k = tid; k < NP; k += 256) {
        float kr[HDIM];
        #pragma unroll
        for (int d = 0; d < HDIM; d++) kr[d] = KTg[(size_t)d * NP + k];
        int ki = k / CC, kj = k - ki*CC;
        for (int j = 0; j < CC; j++) {
            const float4* qp = (const float4*)&Qh[j][0];
            float s0 = 0.f, s1 = 0.f, s2 = 0.f, s3 = 0.f;
            #pragma unroll
            for (int q = 0; q < 8; q++) {
                float4 qv = qp[q];
                s0 = fmaf(kr[q*4+0], qv.x, s0);
                s1 = fmaf(kr[q*4+1], qv.y, s1);
                s2 = fmaf(kr[q*4+2], qv.z, s2);
                s3 = fmaf(kr[q*4+3], qv.w, s3);
            }
            float s = (s0 + s1) + (s2 + s3);
            bool ok = (ki == c) | (kj == c) | (ki == j) | (kj == j);
            S[j][k] = ok ? s * scale : -1e30f;
        }
    }
    __syncthreads();

    // ---- softmax, one warp per row ----
    for (int j = wid; j < CC; j += 8) {
        float mx = -1e30f;
        for (int k = lane; k < NP; k += 32) mx = fmaxf(mx, S[j][k]);
        #pragma unroll
        for (int o = 16; o; o >>= 1) mx = fmaxf(mx, __shfl_xor_sync(~0u, mx, o));
        float sum = 0.f;
        for (int k = lane; k < NP; k += 32) {
            float e = __expf(S[j][k] - mx);
            S[j][k] = e; sum += e;
        }
        #pragma unroll
        for (int o = 16; o; o >>= 1) sum += __shfl_xor_sync(~0u, sum, o);
        float inv = 1.f / sum;
        for (int k = lane; k < NP; k += 32) S[j][k] *= inv;
    }
    __syncthreads();

    // ---- P @ V (coalesced global V, x4 unroll, branchless via pad rows) ----
    {
        const int d = lane, jg = wid;
        const float* vp = Vg + hoff + d;
        float o0 = 0.f, o1 = 0.f, o2 = 0.f;
        for (int k = 0; k < 360; k += 4) {
            float v0 = vp[(size_t)(k+0) * DD];
            float v1 = vp[(size_t)(k+1) * DD];
            float v2 = vp[(size_t)(k+2) * DD];
            float v3 = vp[(size_t)(k+3) * DD];
            float4 sA = *(const float4*)&S[jg   ][k];
            float4 sB = *(const float4*)&S[jg+8 ][k];
            float4 sC = *(const float4*)&S[jg+16][k];
            o0 = fmaf(sA.x, v0, o0); o1 = fmaf(sB.x, v0, o1); o2 = fmaf(sC.x, v0, o2);
            o0 = fmaf(sA.y, v1, o0); o1 = fmaf(sB.y, v1, o1); o2 = fmaf(sC.y, v1, o2);
            o0 = fmaf(sA.z, v2, o0); o1 = fmaf(sB.z, v2, o1); o2 = fmaf(sC.z, v2, o2);
            o0 = fmaf(sA.w, v3, o0); o1 = fmaf(sB.w, v3, o1); o2 = fmaf(sC.w, v3, o2);
        }
        {   // tail k = 360
            float v = vp[(size_t)360 * DD];
            o0 = fmaf(S[jg   ][360], v, o0);
            o1 = fmaf(S[jg+8 ][360], v, o1);
            o2 = fmaf(S[jg+16][360], v, o2);
        }
        Og[jg*DD + hoff + d]     = o0;
        Og[(jg+8)*DD + hoff + d] = o1;
        if (jg + 16 < CC) Og[(jg+16)*DD + hoff + d] = o2;
    }
}

// ---------------- out-proj + fuse + residual ----------------------------------
__global__ __launch_bounds__(256, 2)
void out_fuse(const float* __restrict__ x, float* __restrict__ y) {
    const int c  = blockIdx.z;
    const int m0 = blockIdx.x * 128;
    const int n0 = blockIdx.y * 128;
    __shared__ float As[8][128];
    __shared__ float Bs[8][128];
    const int tid   = threadIdx.x;
    const int ldRow = tid >> 1;
    const int ldCol = (tid & 1) << 2;

    int am = m0 + ldRow; if (am > MQ - 1) am = MQ - 1;
    const float* Ap = g_AO + ((size_t)c*MQ + am) * DD + ldCol;
    const float* Bp = g_Mc + ((size_t)c*DD + n0 + ldRow) * DD + ldCol;

    const int ty = tid >> 4, tx = tid & 15;
    float acc[8][8];
    #pragma unroll
    for (int i = 0; i < 8; i++)
        #pragma unroll
        for (int j = 0; j < 8; j++) acc[i][j] = 0.f;

    for (int kt = 0; kt < DD; kt += 8) {
        float4 a = *(const float4*)(Ap + kt);
        float4 b = *(const float4*)(Bp + kt);
        As[ldCol+0][ldRow]=a.x; As[ldCol+1][ldRow]=a.y;
        As[ldCol+2][ldRow]=a.z; As[ldCol+3][ldRow]=a.w;
        Bs[ldCol+0][ldRow]=b.x; Bs[ldCol+1][ldRow]=b.y;
        Bs[ldCol+2][ldRow]=b.z; Bs[ldCol+3][ldRow]=b.w;
        __syncthreads();
        #pragma unroll
        for (int k = 0; k < 8; k++) {
            float ra[8], rb[8];
            *(float4*)&ra[0] = *(const float4*)&As[k][ty*8];
            *(float4*)&ra[4] = *(const float4*)&As[k][ty*8+4];
            *(float4*)&rb[0] = *(const float4*)&Bs[k][tx*8];
            *(float4*)&rb[4] = *(const float4*)&Bs[k][tx*8+4];
            #pragma unroll
            for (int i = 0; i < 8; i++)
                #pragma unroll
                for (int j = 0; j < 8; j++)
                    acc[i][j] = fmaf(ra[i], rb[j], acc[i][j]);
        }
        __syncthreads();
    }

    const float* bcp = g_bc + c*DD + n0 + tx*8;
    float bv[8];
    #pragma unroll
    for (int j = 0; j < 8; j++) bv[j] = bcp[j];

    #pragma unroll
    for (int i = 0; i < 8; i++) {
        int m = m0 + ty*8 + i;
        if (m >= MQ) break;
        int bb = m / CC, j = m % CC;
        size_t row = (size_t)bb * NP + c * CC + j;
        float*       op = y + row*DD + n0 + tx*8;
        const float* xp = x + row*DD + n0 + tx*8;
        #pragma unroll
        for (int jj = 0; jj < 8; jj += 4) {
            float4 xv = *(const float4*)(xp + jj);
            float4 v;
            v.x = acc[i][jj+0] + bv[jj+0] + xv.x;
            v.y = acc[i][jj+1] + bv[jj+1] + xv.y;
            v.z = acc[i][jj+2] + bv[jj+2] + xv.z;
            v.w = acc[i][jj+3] + bv[jj+3] + xv.w;
            *(float4*)(op + jj) = v;
        }
    }
}

// ---------------- launch (multi-stream fork/join, graph-capturable) -------------
extern "C" void kernel_launch(void* const* d_in, const int* in_sizes, int n_in,
                              void* d_out, int out_size) {
    const float* x      = (const float*)d_in[0];
    const float* w_in   = (const float*)d_in[1];
    const float* b_in   = (const float*)d_in[2];
    const float* w_out  = (const float*)d_in[3];
    const float* b_out  = (const float*)d_in[4];
    const float* w_fuse = (const float*)d_in[5];
    const float* b_fuse = (const float*)d_in[6];
    float* y = (float*)d_out;

    // one-time host-side resource init (streams/events; no device memory)
    static cudaStream_t s1 = nullptr, s2 = nullptr;
    static cudaEvent_t  eb = nullptr, es = nullptr, eq = nullptr, ecb = nullptr;
    if (!s1) {
        cudaStreamCreateWithFlags(&s1, cudaStreamNonBlocking);
        cudaStreamCreateWithFlags(&s2, cudaStreamNonBlocking);
        cudaEventCreateWithFlags(&eb,  cudaEventDisableTiming);
        cudaEventCreateWithFlags(&es,  cudaEventDisableTiming);
        cudaEventCreateWithFlags(&eq,  cudaEventDisableTiming);
        cudaEventCreateWithFlags(&ecb, cudaEventDisableTiming);
        cudaFuncSetAttribute(gemm_kv_mma, cudaFuncAttributeMaxDynamicSharedMemorySize, KV_SMEM);
        cudaFuncSetAttribute(gemm_q_mma,  cudaFuncAttributeMaxDynamicSharedMemorySize, KV_SMEM);
    }

    // fork: comb64+bias (input-only deps) on s1
    cudaEventRecord(eb, 0);
    cudaStreamWaitEvent(s1, eb, 0);
    gemm_comb64<<<dim3(4, 4, CC), 256, 0, s1>>>(w_fuse, w_out);
    bias_comb<<<dim3(CC, DD/8), 256, 0, s1>>>(w_fuse, b_out, b_fuse);
    cudaEventRecord(ecb, s1);

    // main: split, then fork q to s2, kv stays on main
    split_all<<<(N4X + N4W + 255)/256, 256>>>(x, w_in);
    cudaEventRecord(es, 0);
    cudaStreamWaitEvent(s2, es, 0);
    gemm_q_mma<<<dim3(5, 38), 256, KV_SMEM, s2>>>(b_in);
    cudaEventRecord(eq, s2);

    dim3 gkv((MX + 127) / 128, NTOT / 128);   // (91, 76)
    gemm_kv_mma<<<gkv, 256, KV_SMEM>>>(b_in);

    // join: attn needs Q + KV; out_fuse additionally needs Mc/bc (joined here too)
    cudaStreamWaitEvent(0, eq, 0);
    cudaStreamWaitEvent(0, ecb, 0);

    attn_kernel<<<dim3(HH, CC*BB), 256>>>();

    dim3 gq((MQ + 127) / 128, 2, CC);
    out_fuse<<<gq, 256>>>(x, y);
}